// round 7
// baseline (speedup 1.0000x reference)
#include <cuda_runtime.h>
#include <cuda_bf16.h>
#include <cuda_fp16.h>

#define NN 100000
#define EE 1000000
#define HID 64
#define NCHUNK 1024
#define NBLK 98            // ceil(NN / NCHUNK)
#define BN_EPS 1e-5f
#define XS_STRIDE 72       // 64 + 8-half pad -> conflict-free fragment LDS
#define CNT_BLKS 977       // ceil(EE/4 / 256)

// ---------------- scratch ----------------------------------------------------
__device__ __align__(16)  int    g_deg[NN];          // WITHOUT self loop (memset 0)
__device__ __align__(16)  float  g_dinv[NN];
__device__ __align__(16)  int    g_rowptr[NN + 1];
__device__ __align__(16)  int    g_cursor[NN];
__device__ __align__(16)  int    g_src[EE + NN];
__device__ __align__(128) __half g_h[NN * HID];      // fp16 features for the gather
__device__ __align__(128) __half g_x1[NN * HID];     // fp16 layer outputs
__device__ __align__(128) __half g_x2[NN * HID];
__device__ __align__(16)  int    g_bsum[128];
__device__ __align__(16)  __half g_wt[3][HID * HID]; // transposed fp16 weights [n][k], zero-padded

// ---------------- preprocessing ---------------------------------------------

// blocks [0, CNT_BLKS): count in-degrees (4 edges/thread, int4)
// blocks [CNT_BLKS, ...): convert weights + set rowptr[NN]
__global__ void count_kernel(const int4* __restrict__ col4,
                             const float* __restrict__ W1,
                             const float* __restrict__ W2,
                             const float* __restrict__ W3) {
    if (blockIdx.x < CNT_BLKS) {
        int i = blockIdx.x * 256 + threadIdx.x;
        if (i < EE / 4) {
            int4 c = col4[i];
            if ((unsigned)c.x < NN) atomicAdd(&g_deg[c.x], 1);
            if ((unsigned)c.y < NN) atomicAdd(&g_deg[c.y], 1);
            if ((unsigned)c.z < NN) atomicAdd(&g_deg[c.z], 1);
            if ((unsigned)c.w < NN) atomicAdd(&g_deg[c.w], 1);
        }
    } else {
        int i = (blockIdx.x - CNT_BLKS) * 256 + threadIdx.x;
        if (i == 0) g_rowptr[NN] = EE + NN;
        if (i < 3 * HID * HID) {
            int l = i / (HID * HID);
            int rem = i - l * (HID * HID);
            int n = rem >> 6, k = rem & 63;
            const float* W = (l == 0) ? W1 : (l == 1 ? W2 : W3);
            int K = (l == 0) ? 37 : 64;
            float v = (k < K) ? W[k * HID + n] : 0.0f;
            g_wt[l][n * HID + k] = __float2half_rn(v);
        }
    }
}

__global__ void partials_kernel() {
    int tid = threadIdx.x, b = blockIdx.x;
    int base = b * NCHUNK + tid * 4;
    int s = 0;
#pragma unroll
    for (int j = 0; j < 4; j++) {
        int idx = base + j;
        if (idx < NN) {
            int d = g_deg[idx] + 1;          // + self loop
            s += d;
            g_dinv[idx] = rsqrtf((float)d);
        }
    }
    for (int d = 16; d; d >>= 1) s += __shfl_down_sync(0xffffffffu, s, d);
    __shared__ int wsum[8];
    int lane = tid & 31, wid = tid >> 5;
    if (lane == 0) wsum[wid] = s;
    __syncthreads();
    if (tid == 0) {
        int t = 0;
#pragma unroll
        for (int i = 0; i < 8; i++) t += wsum[i];
        g_bsum[b] = t;
    }
}

// fused scan; also places each node's self-loop at rowptr[i], cursor starts +1
__global__ void scan_chunks_kernel() {
    int b = blockIdx.x, tid = threadIdx.x;
    int lane = tid & 31, wid = tid >> 5;

    int p = (tid < b && tid < NBLK) ? g_bsum[tid] : 0;
    for (int d = 16; d; d >>= 1) p += __shfl_down_sync(0xffffffffu, p, d);
    __shared__ int psum[8];
    if (lane == 0) psum[wid] = p;
    __syncthreads();
    __shared__ int chunk_off;
    if (tid == 0) {
        int t = 0;
#pragma unroll
        for (int i = 0; i < 8; i++) t += psum[i];
        chunk_off = t;
    }

    int base = b * NCHUNK + tid * 4;
    int v[4]; int s = 0;
#pragma unroll
    for (int j = 0; j < 4; j++) {
        int idx = base + j;
        v[j] = (idx < NN) ? (g_deg[idx] + 1) : 0;
        s += v[j];
    }
    int x = s;
#pragma unroll
    for (int d = 1; d < 32; d <<= 1) {
        int y = __shfl_up_sync(0xffffffffu, x, d);
        if (lane >= d) x += y;
    }
    __shared__ int wsum[8], woff[8];
    if (lane == 31) wsum[wid] = x;
    __syncthreads();
    if (tid == 0) {
        int run = 0;
#pragma unroll
        for (int i = 0; i < 8; i++) { int t = wsum[i]; woff[i] = run; run += t; }
    }
    __syncthreads();
    int pos = chunk_off + woff[wid] + (x - s);
#pragma unroll
    for (int j = 0; j < 4; j++) {
        int idx = base + j;
        if (idx < NN) {
            g_rowptr[idx] = pos;
            g_src[pos]    = idx;       // self loop first
            g_cursor[idx] = pos + 1;
            pos += v[j];
        }
    }
}

// 4 edges per thread, int4 loads on src and dst streams
__global__ void bin_kernel(const int4* __restrict__ src4,
                           const int4* __restrict__ dst4) {
    int i = blockIdx.x * blockDim.x + threadIdx.x;
    if (i >= EE / 4) return;
    int4 s = src4[i];
    int4 c = dst4[i];
    if ((unsigned)c.x < NN && (unsigned)s.x < NN) g_src[atomicAdd(&g_cursor[c.x], 1)] = s.x;
    if ((unsigned)c.y < NN && (unsigned)s.y < NN) g_src[atomicAdd(&g_cursor[c.y], 1)] = s.y;
    if ((unsigned)c.z < NN && (unsigned)s.z < NN) g_src[atomicAdd(&g_cursor[c.z], 1)] = s.z;
    if ((unsigned)c.w < NN && (unsigned)s.w < NN) g_src[atomicAdd(&g_cursor[c.w], 1)] = s.w;
}

// ---------------- GEMM via mma.sync m16n8k16: h = fp16(dinv * (X @ W)) -------
// 64 nodes / block, 128 threads (4 warps, 16 rows each), K padded to 64.
template <int KIN>
__global__ void __launch_bounds__(128) gemm_mma_kernel(const float* __restrict__ Xext,
                                                       int layer) {
    __shared__ __align__(16) __half Xs[64 * XS_STRIDE];
    __shared__ __align__(16) __half Wts[64 * XS_STRIDE];

    const __half* Wt = g_wt[layer];

    const int tid  = threadIdx.x;
    const int base = blockIdx.x * 64;

    for (int i = tid; i < 64 * 32; i += 128) {
        int n = i >> 5, k2 = (i & 31) * 2;
        *(__half2*)&Wts[n * XS_STRIDE + k2] = *(const __half2*)&Wt[n * HID + k2];
    }

    if constexpr (KIN == 64) {
        const __half* Xh = (layer == 1) ? (const __half*)g_x1 : (const __half*)g_x2;
        for (int i = tid; i < 64 * 16; i += 128) {
            int n = i >> 4, c4 = (i & 15) * 4;   // 4 halves = 8B
            uint2 v = make_uint2(0u, 0u);
            if (base + n < NN) v = *(const uint2*)&Xh[(size_t)(base + n) * 64 + c4];
            *(uint2*)&Xs[n * XS_STRIDE + c4] = v;
        }
    } else {
        for (int i = tid; i < 64 * 64; i += 128) {
            int n = i >> 6, k = i & 63;
            float v = (k < KIN && base + n < NN) ? Xext[(size_t)(base + n) * KIN + k] : 0.0f;
            Xs[n * XS_STRIDE + k] = __float2half_rn(v);
        }
    }
    __syncthreads();

    const int w    = tid >> 5;
    const int lane = tid & 31;
    const int g    = lane >> 2;
    const int t    = lane & 3;

    float acc[8][4];
#pragma unroll
    for (int nt = 0; nt < 8; nt++)
#pragma unroll
        for (int q = 0; q < 4; q++) acc[nt][q] = 0.0f;

    const int rowA0 = (16 * w + g)     * XS_STRIDE;
    const int rowA1 = (16 * w + g + 8) * XS_STRIDE;

#pragma unroll
    for (int kt = 0; kt < 4; kt++) {
        const int kb = kt * 16 + 2 * t;
        unsigned a0 = *(const unsigned*)&Xs[rowA0 + kb];
        unsigned a1 = *(const unsigned*)&Xs[rowA1 + kb];
        unsigned a2 = *(const unsigned*)&Xs[rowA0 + kb + 8];
        unsigned a3 = *(const unsigned*)&Xs[rowA1 + kb + 8];
#pragma unroll
        for (int nt = 0; nt < 8; nt++) {
            unsigned b0 = *(const unsigned*)&Wts[(8 * nt + g) * XS_STRIDE + kb];
            unsigned b1 = *(const unsigned*)&Wts[(8 * nt + g) * XS_STRIDE + kb + 8];
            asm volatile(
                "mma.sync.aligned.m16n8k16.row.col.f32.f16.f16.f32 "
                "{%0,%1,%2,%3}, {%4,%5,%6,%7}, {%8,%9}, {%0,%1,%2,%3};"
                : "+f"(acc[nt][0]), "+f"(acc[nt][1]), "+f"(acc[nt][2]), "+f"(acc[nt][3])
                : "r"(a0), "r"(a1), "r"(a2), "r"(a3), "r"(b0), "r"(b1));
        }
    }

    int r0 = base + 16 * w + g;
    int r1 = r0 + 8;
    float d0 = (r0 < NN) ? g_dinv[r0] : 0.0f;
    float d1 = (r1 < NN) ? g_dinv[r1] : 0.0f;
#pragma unroll
    for (int nt = 0; nt < 8; nt++) {
        int col = 8 * nt + 2 * t;
        if (r0 < NN)
            *(__half2*)&g_h[r0 * HID + col] = __floats2half2_rn(d0 * acc[nt][0], d0 * acc[nt][1]);
        if (r1 < NN)
            *(__half2*)&g_h[r1 * HID + col] = __floats2half2_rn(d1 * acc[nt][2], d1 * acc[nt][3]);
    }
}

// ---------------- SpMM (gather fp16, CSR) + fused BN/ReLU/residual -----------
// one warp per 4 nodes, 2 cols per lane, int4-vectorized index stream, MLP=8
__global__ void spmm_epi_kernel(int layer,
                                const float* __restrict__ bias,
                                const float* __restrict__ gamma,
                                const float* __restrict__ beta,
                                const float* __restrict__ mean,
                                const float* __restrict__ var,
                                float* __restrict__ out_final) {
    int w = (blockIdx.x * blockDim.x + threadIdx.x) >> 5;
    int n0 = w * 4;
    if (n0 >= NN) return;
    int lane = threadIdx.x & 31;
    int c = lane * 2;

    const __half* __restrict__ H = g_h;

    float bx = bias[c],  by = bias[c + 1];
    float mx = mean[c],  my = mean[c + 1];
    float btx = beta[c], bty = beta[c + 1];
    float scx = gamma[c]     * rsqrtf(var[c]     + BN_EPS);
    float scy = gamma[c + 1] * rsqrtf(var[c + 1] + BN_EPS);

#pragma unroll
    for (int j = 0; j < 4; j++) {
        int node = n0 + j;
        if (node >= NN) break;
        int beg = g_rowptr[node];
        int end = g_rowptr[node + 1];

        float2 a[8];
#pragma unroll
        for (int q = 0; q < 8; q++) a[q] = make_float2(0.f, 0.f);

        int e = beg;
        // peel to 16B alignment of g_src
        while (e < end && (e & 3)) {
            int s = g_src[e++];
            float2 v = __half22float2(*(const __half2*)(H + s * HID + c));
            a[0].x += v.x; a[0].y += v.y;
        }
        for (; e + 7 < end; e += 8) {
            int4 i0 = *(const int4*)&g_src[e];
            int4 i1 = *(const int4*)&g_src[e + 4];
            float2 v0 = __half22float2(*(const __half2*)(H + i0.x * HID + c));
            float2 v1 = __half22float2(*(const __half2*)(H + i0.y * HID + c));
            float2 v2 = __half22float2(*(const __half2*)(H + i0.z * HID + c));
            float2 v3 = __half22float2(*(const __half2*)(H + i0.w * HID + c));
            float2 v4 = __half22float2(*(const __half2*)(H + i1.x * HID + c));
            float2 v5 = __half22float2(*(const __half2*)(H + i1.y * HID + c));
            float2 v6 = __half22float2(*(const __half2*)(H + i1.z * HID + c));
            float2 v7 = __half22float2(*(const __half2*)(H + i1.w * HID + c));
            a[0].x += v0.x; a[0].y += v0.y;
            a[1].x += v1.x; a[1].y += v1.y;
            a[2].x += v2.x; a[2].y += v2.y;
            a[3].x += v3.x; a[3].y += v3.y;
            a[4].x += v4.x; a[4].y += v4.y;
            a[5].x += v5.x; a[5].y += v5.y;
            a[6].x += v6.x; a[6].y += v6.y;
            a[7].x += v7.x; a[7].y += v7.y;
        }
        if (e + 3 < end) {
            int4 i0 = *(const int4*)&g_src[e];
            float2 v0 = __half22float2(*(const __half2*)(H + i0.x * HID + c));
            float2 v1 = __half22float2(*(const __half2*)(H + i0.y * HID + c));
            float2 v2 = __half22float2(*(const __half2*)(H + i0.z * HID + c));
            float2 v3 = __half22float2(*(const __half2*)(H + i0.w * HID + c));
            a[0].x += v0.x; a[0].y += v0.y;
            a[1].x += v1.x; a[1].y += v1.y;
            a[2].x += v2.x; a[2].y += v2.y;
            a[3].x += v3.x; a[3].y += v3.y;
            e += 4;
        }
        while (e < end) {
            int s = g_src[e++];
            float2 v = __half22float2(*(const __half2*)(H + s * HID + c));
            a[0].x += v.x; a[0].y += v.y;
        }

        float sx = ((a[0].x + a[1].x) + (a[2].x + a[3].x)) +
                   ((a[4].x + a[5].x) + (a[6].x + a[7].x));
        float sy = ((a[0].y + a[1].y) + (a[2].y + a[3].y)) +
                   ((a[4].y + a[5].y) + (a[6].y + a[7].y));

        float di = g_dinv[node];
        float vx = (sx * di + bx - mx) * scx + btx;
        float vy = (sy * di + by - my) * scy + bty;
        vx = fmaxf(vx, 0.0f);
        vy = fmaxf(vy, 0.0f);

        if (layer == 0) {
            *(__half2*)&g_x1[node * HID + c] = __floats2half2_rn(vx, vy);
        } else if (layer == 1) {
            float2 r = __half22float2(*(const __half2*)&g_x1[node * HID + c]);
            *(__half2*)&g_x2[node * HID + c] = __floats2half2_rn(vx + r.x, vy + r.y);
        } else {
            float2 r = __half22float2(*(const __half2*)&g_x2[node * HID + c]);
            *(float2*)(out_final + node * HID + c) = make_float2(vx + r.x, vy + r.y);
        }
    }
}

// ---------------- launch -----------------------------------------------------
extern "C" void kernel_launch(void* const* d_in, const int* in_sizes, int n_in,
                              void* d_out, int out_size) {
    const float* x   = (const float*)d_in[0];
    const int*   ei  = (const int*)d_in[1];     // int32 (JAX default, no x64)
    const float* W1  = (const float*)d_in[2];
    const float* W2  = (const float*)d_in[3];
    const float* W3  = (const float*)d_in[4];
    const float* b   = (const float*)d_in[5];
    const float* gma = (const float*)d_in[6];
    const float* bta = (const float*)d_in[7];
    const float* mu  = (const float*)d_in[8];
    const float* var = (const float*)d_in[9];
    float* out = (float*)d_out;

    void* deg_ptr = nullptr;
    cudaGetSymbolAddress(&deg_ptr, g_deg);
    cudaMemsetAsync(deg_ptr, 0, NN * sizeof(int));

    count_kernel<<<CNT_BLKS + 48, 256>>>((const int4*)(ei + EE), W1, W2, W3);
    partials_kernel<<<NBLK, 256>>>();
    scan_chunks_kernel<<<NBLK, 256>>>();
    bin_kernel<<<(EE / 4 + 255) / 256, 256>>>((const int4*)ei, (const int4*)(ei + EE));

    const int GEMM_BLOCKS = (NN + 63) / 64;
    const int SPMM_BLOCKS = ((NN + 3) / 4 * 32 + 255) / 256;

    gemm_mma_kernel<37><<<GEMM_BLOCKS, 128>>>(x, 0);
    spmm_epi_kernel<<<SPMM_BLOCKS, 256>>>(0, b,       gma,       bta,       mu,       var,       out);
    gemm_mma_kernel<64><<<GEMM_BLOCKS, 128>>>(nullptr, 1);
    spmm_epi_kernel<<<SPMM_BLOCKS, 256>>>(1, b + 64,  gma + 64,  bta + 64,  mu + 64,  var + 64,  out);
    gemm_mma_kernel<64><<<GEMM_BLOCKS, 128>>>(nullptr, 2);
    spmm_epi_kernel<<<SPMM_BLOCKS, 256>>>(2, b + 128, gma + 128, bta + 128, mu + 128, var + 128, out);
}

// round 8
// speedup vs baseline: 1.0990x; 1.0990x over previous
#include <cuda_runtime.h>
#include <cuda_bf16.h>
#include <cuda_fp16.h>

#define NN 100000
#define EE 1000000
#define HID 64
#define NCHUNK 1024
#define NBLK 98            // ceil(NN / NCHUNK)
#define BN_EPS 1e-5f
#define XS_STRIDE 72       // 64 + 8-half pad -> conflict-free fragment LDS
#define CNT_BLKS 977       // ceil(EE/4 / 256)

// ---------------- scratch ----------------------------------------------------
__device__ __align__(16)  int    g_deg[NN];          // WITHOUT self loop (memset 0)
__device__ __align__(16)  float  g_dinv[NN];
__device__ __align__(16)  int    g_rowptr[NN + 1];
__device__ __align__(16)  int    g_cursor[NN];
__device__ __align__(16)  int    g_src[EE + NN];
__device__ __align__(128) __half g_h[NN * HID];      // fp16 features for the gather
__device__ __align__(128) __half g_x1[NN * HID];     // fp16 layer outputs
__device__ __align__(128) __half g_x2[NN * HID];
__device__ __align__(16)  int    g_bsum[128];
__device__ __align__(16)  __half g_wt[3][HID * HID]; // transposed fp16 weights [n][k], zero-padded

// ---------------- preprocessing ---------------------------------------------

// blocks [0, CNT_BLKS): count in-degrees (4 edges/thread, int4)
// blocks [CNT_BLKS, ...): convert weights + set rowptr[NN]
__global__ void count_kernel(const int4* __restrict__ col4,
                             const float* __restrict__ W1,
                             const float* __restrict__ W2,
                             const float* __restrict__ W3) {
    if (blockIdx.x < CNT_BLKS) {
        int i = blockIdx.x * 256 + threadIdx.x;
        if (i < EE / 4) {
            int4 c = col4[i];
            if ((unsigned)c.x < NN) atomicAdd(&g_deg[c.x], 1);
            if ((unsigned)c.y < NN) atomicAdd(&g_deg[c.y], 1);
            if ((unsigned)c.z < NN) atomicAdd(&g_deg[c.z], 1);
            if ((unsigned)c.w < NN) atomicAdd(&g_deg[c.w], 1);
        }
    } else {
        int i = (blockIdx.x - CNT_BLKS) * 256 + threadIdx.x;
        if (i == 0) g_rowptr[NN] = EE + NN;
        if (i < 3 * HID * HID) {
            int l = i / (HID * HID);
            int rem = i - l * (HID * HID);
            int n = rem >> 6, k = rem & 63;
            const float* W = (l == 0) ? W1 : (l == 1 ? W2 : W3);
            int K = (l == 0) ? 37 : 64;
            float v = (k < K) ? W[k * HID + n] : 0.0f;
            g_wt[l][n * HID + k] = __float2half_rn(v);
        }
    }
}

__global__ void partials_kernel() {
    int tid = threadIdx.x, b = blockIdx.x;
    int base = b * NCHUNK + tid * 4;
    int s = 0;
#pragma unroll
    for (int j = 0; j < 4; j++) {
        int idx = base + j;
        if (idx < NN) {
            int d = g_deg[idx] + 1;          // + self loop
            s += d;
            g_dinv[idx] = rsqrtf((float)d);
        }
    }
    for (int d = 16; d; d >>= 1) s += __shfl_down_sync(0xffffffffu, s, d);
    __shared__ int wsum[8];
    int lane = tid & 31, wid = tid >> 5;
    if (lane == 0) wsum[wid] = s;
    __syncthreads();
    if (tid == 0) {
        int t = 0;
#pragma unroll
        for (int i = 0; i < 8; i++) t += wsum[i];
        g_bsum[b] = t;
    }
}

// fused scan; also places each node's self-loop at rowptr[i], cursor starts +1
__global__ void scan_chunks_kernel() {
    int b = blockIdx.x, tid = threadIdx.x;
    int lane = tid & 31, wid = tid >> 5;

    int p = (tid < b && tid < NBLK) ? g_bsum[tid] : 0;
    for (int d = 16; d; d >>= 1) p += __shfl_down_sync(0xffffffffu, p, d);
    __shared__ int psum[8];
    if (lane == 0) psum[wid] = p;
    __syncthreads();
    __shared__ int chunk_off;
    if (tid == 0) {
        int t = 0;
#pragma unroll
        for (int i = 0; i < 8; i++) t += psum[i];
        chunk_off = t;
    }

    int base = b * NCHUNK + tid * 4;
    int v[4]; int s = 0;
#pragma unroll
    for (int j = 0; j < 4; j++) {
        int idx = base + j;
        v[j] = (idx < NN) ? (g_deg[idx] + 1) : 0;
        s += v[j];
    }
    int x = s;
#pragma unroll
    for (int d = 1; d < 32; d <<= 1) {
        int y = __shfl_up_sync(0xffffffffu, x, d);
        if (lane >= d) x += y;
    }
    __shared__ int wsum[8], woff[8];
    if (lane == 31) wsum[wid] = x;
    __syncthreads();
    if (tid == 0) {
        int run = 0;
#pragma unroll
        for (int i = 0; i < 8; i++) { int t = wsum[i]; woff[i] = run; run += t; }
    }
    __syncthreads();
    int pos = chunk_off + woff[wid] + (x - s);
#pragma unroll
    for (int j = 0; j < 4; j++) {
        int idx = base + j;
        if (idx < NN) {
            g_rowptr[idx] = pos;
            g_src[pos]    = idx;       // self loop first
            g_cursor[idx] = pos + 1;
            pos += v[j];
        }
    }
}

// scalar: 1 edge per thread (atomic latency hidden by warp parallelism)
__global__ void bin_kernel(const int* __restrict__ ei) {
    int i = blockIdx.x * blockDim.x + threadIdx.x;
    if (i >= EE) return;
    unsigned s = (unsigned)ei[i];
    unsigned c = (unsigned)ei[EE + i];
    if (s >= NN || c >= NN) return;
    int p = atomicAdd(&g_cursor[c], 1);
    g_src[p] = (int)s;
}

// ---------------- GEMM via mma.sync m16n8k16: h = fp16(dinv * (X @ W)) -------
// 64 nodes / block, 128 threads (4 warps, 16 rows each), K padded to 64.
template <int KIN>
__global__ void __launch_bounds__(128) gemm_mma_kernel(const float* __restrict__ Xext,
                                                       int layer) {
    __shared__ __align__(16) __half Xs[64 * XS_STRIDE];
    __shared__ __align__(16) __half Wts[64 * XS_STRIDE];

    const __half* Wt = g_wt[layer];

    const int tid  = threadIdx.x;
    const int base = blockIdx.x * 64;

    for (int i = tid; i < 64 * 32; i += 128) {
        int n = i >> 5, k2 = (i & 31) * 2;
        *(__half2*)&Wts[n * XS_STRIDE + k2] = *(const __half2*)&Wt[n * HID + k2];
    }

    if constexpr (KIN == 64) {
        const __half* Xh = (layer == 1) ? (const __half*)g_x1 : (const __half*)g_x2;
        for (int i = tid; i < 64 * 16; i += 128) {
            int n = i >> 4, c4 = (i & 15) * 4;   // 4 halves = 8B
            uint2 v = make_uint2(0u, 0u);
            if (base + n < NN) v = *(const uint2*)&Xh[(size_t)(base + n) * 64 + c4];
            *(uint2*)&Xs[n * XS_STRIDE + c4] = v;
        }
    } else {
        for (int i = tid; i < 64 * 64; i += 128) {
            int n = i >> 6, k = i & 63;
            float v = (k < KIN && base + n < NN) ? Xext[(size_t)(base + n) * KIN + k] : 0.0f;
            Xs[n * XS_STRIDE + k] = __float2half_rn(v);
        }
    }
    __syncthreads();

    const int w    = tid >> 5;
    const int lane = tid & 31;
    const int g    = lane >> 2;
    const int t    = lane & 3;

    float acc[8][4];
#pragma unroll
    for (int nt = 0; nt < 8; nt++)
#pragma unroll
        for (int q = 0; q < 4; q++) acc[nt][q] = 0.0f;

    const int rowA0 = (16 * w + g)     * XS_STRIDE;
    const int rowA1 = (16 * w + g + 8) * XS_STRIDE;

#pragma unroll
    for (int kt = 0; kt < 4; kt++) {
        const int kb = kt * 16 + 2 * t;
        unsigned a0 = *(const unsigned*)&Xs[rowA0 + kb];
        unsigned a1 = *(const unsigned*)&Xs[rowA1 + kb];
        unsigned a2 = *(const unsigned*)&Xs[rowA0 + kb + 8];
        unsigned a3 = *(const unsigned*)&Xs[rowA1 + kb + 8];
#pragma unroll
        for (int nt = 0; nt < 8; nt++) {
            unsigned b0 = *(const unsigned*)&Wts[(8 * nt + g) * XS_STRIDE + kb];
            unsigned b1 = *(const unsigned*)&Wts[(8 * nt + g) * XS_STRIDE + kb + 8];
            asm volatile(
                "mma.sync.aligned.m16n8k16.row.col.f32.f16.f16.f32 "
                "{%0,%1,%2,%3}, {%4,%5,%6,%7}, {%8,%9}, {%0,%1,%2,%3};"
                : "+f"(acc[nt][0]), "+f"(acc[nt][1]), "+f"(acc[nt][2]), "+f"(acc[nt][3])
                : "r"(a0), "r"(a1), "r"(a2), "r"(a3), "r"(b0), "r"(b1));
        }
    }

    int r0 = base + 16 * w + g;
    int r1 = r0 + 8;
    float d0 = (r0 < NN) ? g_dinv[r0] : 0.0f;
    float d1 = (r1 < NN) ? g_dinv[r1] : 0.0f;
#pragma unroll
    for (int nt = 0; nt < 8; nt++) {
        int col = 8 * nt + 2 * t;
        if (r0 < NN)
            *(__half2*)&g_h[r0 * HID + col] = __floats2half2_rn(d0 * acc[nt][0], d0 * acc[nt][1]);
        if (r1 < NN)
            *(__half2*)&g_h[r1 * HID + col] = __floats2half2_rn(d1 * acc[nt][2], d1 * acc[nt][3]);
    }
}

// ---------------- SpMM (gather fp16, CSR) + fused BN/ReLU/residual -----------
// one warp per 4 nodes, 2 cols per lane, unroll-8 (MLP=8), params hoisted
__global__ void spmm_epi_kernel(int layer,
                                const float* __restrict__ bias,
                                const float* __restrict__ gamma,
                                const float* __restrict__ beta,
                                const float* __restrict__ mean,
                                const float* __restrict__ var,
                                float* __restrict__ out_final) {
    int w = (blockIdx.x * blockDim.x + threadIdx.x) >> 5;
    int n0 = w * 4;
    if (n0 >= NN) return;
    int lane = threadIdx.x & 31;
    int c = lane * 2;

    const __half* __restrict__ H = g_h;

    float bx = bias[c],  by = bias[c + 1];
    float mx = mean[c],  my = mean[c + 1];
    float btx = beta[c], bty = beta[c + 1];
    float scx = gamma[c]     * rsqrtf(var[c]     + BN_EPS);
    float scy = gamma[c + 1] * rsqrtf(var[c + 1] + BN_EPS);

#pragma unroll
    for (int j = 0; j < 4; j++) {
        int node = n0 + j;
        if (node >= NN) break;
        int beg = g_rowptr[node];
        int end = g_rowptr[node + 1];

        float2 a[8];
#pragma unroll
        for (int q = 0; q < 8; q++) a[q] = make_float2(0.f, 0.f);

        int e = beg;
        for (; e + 7 < end; e += 8) {
            int   s[8];
            float2 v[8];
#pragma unroll
            for (int q = 0; q < 8; q++) s[q] = g_src[e + q];
#pragma unroll
            for (int q = 0; q < 8; q++)
                v[q] = __half22float2(*(const __half2*)(H + s[q] * HID + c));
#pragma unroll
            for (int q = 0; q < 8; q++) { a[q].x += v[q].x; a[q].y += v[q].y; }
        }
        for (; e < end; e++) {
            int s = g_src[e];
            float2 v = __half22float2(*(const __half2*)(H + s * HID + c));
            a[0].x += v.x; a[0].y += v.y;
        }

        float sx = ((a[0].x + a[1].x) + (a[2].x + a[3].x)) +
                   ((a[4].x + a[5].x) + (a[6].x + a[7].x));
        float sy = ((a[0].y + a[1].y) + (a[2].y + a[3].y)) +
                   ((a[4].y + a[5].y) + (a[6].y + a[7].y));

        float di = g_dinv[node];
        float vx = (sx * di + bx - mx) * scx + btx;
        float vy = (sy * di + by - my) * scy + bty;
        vx = fmaxf(vx, 0.0f);
        vy = fmaxf(vy, 0.0f);

        if (layer == 0) {
            *(__half2*)&g_x1[node * HID + c] = __floats2half2_rn(vx, vy);
        } else if (layer == 1) {
            float2 r = __half22float2(*(const __half2*)&g_x1[node * HID + c]);
            *(__half2*)&g_x2[node * HID + c] = __floats2half2_rn(vx + r.x, vy + r.y);
        } else {
            float2 r = __half22float2(*(const __half2*)&g_x2[node * HID + c]);
            *(float2*)(out_final + node * HID + c) = make_float2(vx + r.x, vy + r.y);
        }
    }
}

// ---------------- launch -----------------------------------------------------
extern "C" void kernel_launch(void* const* d_in, const int* in_sizes, int n_in,
                              void* d_out, int out_size) {
    const float* x   = (const float*)d_in[0];
    const int*   ei  = (const int*)d_in[1];     // int32 (JAX default, no x64)
    const float* W1  = (const float*)d_in[2];
    const float* W2  = (const float*)d_in[3];
    const float* W3  = (const float*)d_in[4];
    const float* b   = (const float*)d_in[5];
    const float* gma = (const float*)d_in[6];
    const float* bta = (const float*)d_in[7];
    const float* mu  = (const float*)d_in[8];
    const float* var = (const float*)d_in[9];
    float* out = (float*)d_out;

    void* deg_ptr = nullptr;
    cudaGetSymbolAddress(&deg_ptr, g_deg);
    cudaMemsetAsync(deg_ptr, 0, NN * sizeof(int));

    count_kernel<<<CNT_BLKS + 48, 256>>>((const int4*)(ei + EE), W1, W2, W3);
    partials_kernel<<<NBLK, 256>>>();
    scan_chunks_kernel<<<NBLK, 256>>>();
    bin_kernel<<<(EE + 255) / 256, 256>>>(ei);

    const int GEMM_BLOCKS = (NN + 63) / 64;
    const int SPMM_BLOCKS = ((NN + 3) / 4 * 32 + 255) / 256;

    gemm_mma_kernel<37><<<GEMM_BLOCKS, 128>>>(x, 0);
    spmm_epi_kernel<<<SPMM_BLOCKS, 256>>>(0, b,       gma,       bta,       mu,       var,       out);
    gemm_mma_kernel<64><<<GEMM_BLOCKS, 128>>>(nullptr, 1);
    spmm_epi_kernel<<<SPMM_BLOCKS, 256>>>(1, b + 64,  gma + 64,  bta + 64,  mu + 64,  var + 64,  out);
    gemm_mma_kernel<64><<<GEMM_BLOCKS, 128>>>(nullptr, 2);
    spmm_epi_kernel<<<SPMM_BLOCKS, 256>>>(2, b + 128, gma + 128, bta + 128, mu + 128, var + 128, out);
}

// round 9
// speedup vs baseline: 1.1481x; 1.0446x over previous
#include <cuda_runtime.h>
#include <cuda_bf16.h>
#include <cuda_fp16.h>

#define NN 100000
#define EE 1000000
#define HID 64
#define NCHUNK 256
#define NBLK 391           // ceil(NN / 256)
#define BN_EPS 1e-5f
#define XS_STRIDE 72       // 64 + 8-half pad -> conflict-free fragment LDS
#define CNT_BLKS 977       // ceil(EE/4 / 256)

// ---------------- scratch ----------------------------------------------------
__device__ __align__(16)  int    g_deg[NN];          // WITHOUT self loop (memset 0)
__device__ __align__(16)  float  g_dinv[NN];
__device__ __align__(16)  int    g_rowptr[NN + 1];
__device__ __align__(16)  int    g_cursor[NN];
__device__ __align__(16)  int    g_src[EE + NN];
__device__ __align__(128) __half g_h[NN * HID];      // fp16 features for the gather
__device__ __align__(128) __half g_x1[NN * HID];     // fp16 layer outputs
__device__ __align__(128) __half g_x2[NN * HID];
__device__ __align__(16)  int    g_bsum[512];
__device__ __align__(16)  __half g_wt[3][HID * HID]; // transposed fp16 weights [n][k], zero-padded

// ---------------- preprocessing ---------------------------------------------

// blocks [0, CNT_BLKS): count in-degrees (4 edges/thread, int4)
// blocks [CNT_BLKS, ...): convert weights + set rowptr[NN]
__global__ void count_kernel(const int4* __restrict__ col4,
                             const float* __restrict__ W1,
                             const float* __restrict__ W2,
                             const float* __restrict__ W3) {
    if (blockIdx.x < CNT_BLKS) {
        int i = blockIdx.x * 256 + threadIdx.x;
        if (i < EE / 4) {
            int4 c = col4[i];
            if ((unsigned)c.x < NN) atomicAdd(&g_deg[c.x], 1);
            if ((unsigned)c.y < NN) atomicAdd(&g_deg[c.y], 1);
            if ((unsigned)c.z < NN) atomicAdd(&g_deg[c.z], 1);
            if ((unsigned)c.w < NN) atomicAdd(&g_deg[c.w], 1);
        }
    } else {
        int i = (blockIdx.x - CNT_BLKS) * 256 + threadIdx.x;
        if (i == 0) g_rowptr[NN] = EE + NN;
        if (i < 3 * HID * HID) {
            int l = i / (HID * HID);
            int rem = i - l * (HID * HID);
            int n = rem >> 6, k = rem & 63;
            const float* W = (l == 0) ? W1 : (l == 1 ? W2 : W3);
            int K = (l == 0) ? 37 : 64;
            float v = (k < K) ? W[k * HID + n] : 0.0f;
            g_wt[l][n * HID + k] = __float2half_rn(v);
        }
    }
}

// 1 node per thread, 391 blocks: per-256-chunk degree sums + dinv
__global__ void partials_kernel() {
    int b = blockIdx.x, tid = threadIdx.x;
    int idx = b * NCHUNK + tid;
    int d = 0;
    if (idx < NN) {
        d = g_deg[idx] + 1;              // + self loop
        g_dinv[idx] = rsqrtf((float)d);
    }
    int s = d;
    for (int o = 16; o; o >>= 1) s += __shfl_down_sync(0xffffffffu, s, o);
    __shared__ int wsum[8];
    int lane = tid & 31, wid = tid >> 5;
    if (lane == 0) wsum[wid] = s;
    __syncthreads();
    if (tid == 0) {
        int t = 0;
#pragma unroll
        for (int i = 0; i < 8; i++) t += wsum[i];
        g_bsum[b] = t;
    }
}

// fused scan; places each node's self-loop at rowptr[i], cursor starts +1
__global__ void scan_chunks_kernel() {
    int b = blockIdx.x, tid = threadIdx.x;
    int lane = tid & 31, wid = tid >> 5;

    // chunk_off = sum of g_bsum[t] for t < b (strided loop + block reduce)
    int p = 0;
    for (int t = tid; t < b; t += 256) p += g_bsum[t];
    for (int o = 16; o; o >>= 1) p += __shfl_down_sync(0xffffffffu, p, o);
    __shared__ int psum[8];
    if (lane == 0) psum[wid] = p;
    __syncthreads();
    __shared__ int chunk_off;
    if (tid == 0) {
        int t = 0;
#pragma unroll
        for (int i = 0; i < 8; i++) t += psum[i];
        chunk_off = t;
    }

    int idx = b * NCHUNK + tid;
    int v = (idx < NN) ? (g_deg[idx] + 1) : 0;

    int x = v;
#pragma unroll
    for (int d = 1; d < 32; d <<= 1) {
        int y = __shfl_up_sync(0xffffffffu, x, d);
        if (lane >= d) x += y;
    }
    __shared__ int wsum[8], woff[8];
    if (lane == 31) wsum[wid] = x;
    __syncthreads();
    if (tid == 0) {
        int run = 0;
#pragma unroll
        for (int i = 0; i < 8; i++) { int t = wsum[i]; woff[i] = run; run += t; }
    }
    __syncthreads();

    if (idx < NN) {
        int pos = chunk_off + woff[wid] + (x - v);
        g_rowptr[idx] = pos;
        g_src[pos]    = idx;           // self loop first
        g_cursor[idx] = pos + 1;
    }
}

// scalar: 1 edge per thread
__global__ void bin_kernel(const int* __restrict__ ei) {
    int i = blockIdx.x * blockDim.x + threadIdx.x;
    if (i >= EE) return;
    unsigned s = (unsigned)ei[i];
    unsigned c = (unsigned)ei[EE + i];
    if (s >= NN || c >= NN) return;
    int p = atomicAdd(&g_cursor[c], 1);
    g_src[p] = (int)s;
}

// ---------------- GEMM via mma.sync m16n8k16: h = fp16(dinv * (X @ W)) -------
// 64 nodes / block, 128 threads (4 warps, 16 rows each), K padded to 64.
template <int KIN>
__global__ void __launch_bounds__(128) gemm_mma_kernel(const float* __restrict__ Xext,
                                                       int layer) {
    __shared__ __align__(16) __half Xs[64 * XS_STRIDE];
    __shared__ __align__(16) __half Wts[64 * XS_STRIDE];

    const __half* Wt = g_wt[layer];

    const int tid  = threadIdx.x;
    const int base = blockIdx.x * 64;

    for (int i = tid; i < 64 * 32; i += 128) {
        int n = i >> 5, k2 = (i & 31) * 2;
        *(__half2*)&Wts[n * XS_STRIDE + k2] = *(const __half2*)&Wt[n * HID + k2];
    }

    if constexpr (KIN == 64) {
        const __half* Xh = (layer == 1) ? (const __half*)g_x1 : (const __half*)g_x2;
        for (int i = tid; i < 64 * 16; i += 128) {
            int n = i >> 4, c4 = (i & 15) * 4;   // 4 halves = 8B
            uint2 v = make_uint2(0u, 0u);
            if (base + n < NN) v = *(const uint2*)&Xh[(size_t)(base + n) * 64 + c4];
            *(uint2*)&Xs[n * XS_STRIDE + c4] = v;
        }
    } else {
        for (int i = tid; i < 64 * 64; i += 128) {
            int n = i >> 6, k = i & 63;
            float v = (k < KIN && base + n < NN) ? Xext[(size_t)(base + n) * KIN + k] : 0.0f;
            Xs[n * XS_STRIDE + k] = __float2half_rn(v);
        }
    }
    __syncthreads();

    const int w    = tid >> 5;
    const int lane = tid & 31;
    const int g    = lane >> 2;
    const int t    = lane & 3;

    float acc[8][4];
#pragma unroll
    for (int nt = 0; nt < 8; nt++)
#pragma unroll
        for (int q = 0; q < 4; q++) acc[nt][q] = 0.0f;

    const int rowA0 = (16 * w + g)     * XS_STRIDE;
    const int rowA1 = (16 * w + g + 8) * XS_STRIDE;

#pragma unroll
    for (int kt = 0; kt < 4; kt++) {
        const int kb = kt * 16 + 2 * t;
        unsigned a0 = *(const unsigned*)&Xs[rowA0 + kb];
        unsigned a1 = *(const unsigned*)&Xs[rowA1 + kb];
        unsigned a2 = *(const unsigned*)&Xs[rowA0 + kb + 8];
        unsigned a3 = *(const unsigned*)&Xs[rowA1 + kb + 8];
#pragma unroll
        for (int nt = 0; nt < 8; nt++) {
            unsigned b0 = *(const unsigned*)&Wts[(8 * nt + g) * XS_STRIDE + kb];
            unsigned b1 = *(const unsigned*)&Wts[(8 * nt + g) * XS_STRIDE + kb + 8];
            asm volatile(
                "mma.sync.aligned.m16n8k16.row.col.f32.f16.f16.f32 "
                "{%0,%1,%2,%3}, {%4,%5,%6,%7}, {%8,%9}, {%0,%1,%2,%3};"
                : "+f"(acc[nt][0]), "+f"(acc[nt][1]), "+f"(acc[nt][2]), "+f"(acc[nt][3])
                : "r"(a0), "r"(a1), "r"(a2), "r"(a3), "r"(b0), "r"(b1));
        }
    }

    int r0 = base + 16 * w + g;
    int r1 = r0 + 8;
    float d0 = (r0 < NN) ? g_dinv[r0] : 0.0f;
    float d1 = (r1 < NN) ? g_dinv[r1] : 0.0f;
#pragma unroll
    for (int nt = 0; nt < 8; nt++) {
        int col = 8 * nt + 2 * t;
        if (r0 < NN)
            *(__half2*)&g_h[r0 * HID + col] = __floats2half2_rn(d0 * acc[nt][0], d0 * acc[nt][1]);
        if (r1 < NN)
            *(__half2*)&g_h[r1 * HID + col] = __floats2half2_rn(d1 * acc[nt][2], d1 * acc[nt][3]);
    }
}

// ---------------- SpMM (gather fp16, CSR) + fused BN/ReLU/residual -----------
// one warp per 4 nodes, 2 cols per lane, unroll-8 (MLP=8), params hoisted
__global__ void spmm_epi_kernel(int layer,
                                const float* __restrict__ bias,
                                const float* __restrict__ gamma,
                                const float* __restrict__ beta,
                                const float* __restrict__ mean,
                                const float* __restrict__ var,
                                float* __restrict__ out_final) {
    int w = (blockIdx.x * blockDim.x + threadIdx.x) >> 5;
    int n0 = w * 4;
    if (n0 >= NN) return;
    int lane = threadIdx.x & 31;
    int c = lane * 2;

    const __half* __restrict__ H = g_h;

    float bx = bias[c],  by = bias[c + 1];
    float mx = mean[c],  my = mean[c + 1];
    float btx = beta[c], bty = beta[c + 1];
    float scx = gamma[c]     * rsqrtf(var[c]     + BN_EPS);
    float scy = gamma[c + 1] * rsqrtf(var[c + 1] + BN_EPS);

#pragma unroll
    for (int j = 0; j < 4; j++) {
        int node = n0 + j;
        if (node >= NN) break;
        int beg = g_rowptr[node];
        int end = g_rowptr[node + 1];

        float2 a[8];
#pragma unroll
        for (int q = 0; q < 8; q++) a[q] = make_float2(0.f, 0.f);

        int e = beg;
        for (; e + 7 < end; e += 8) {
            int   s[8];
            float2 v[8];
#pragma unroll
            for (int q = 0; q < 8; q++) s[q] = g_src[e + q];
#pragma unroll
            for (int q = 0; q < 8; q++)
                v[q] = __half22float2(*(const __half2*)(H + s[q] * HID + c));
#pragma unroll
            for (int q = 0; q < 8; q++) { a[q].x += v[q].x; a[q].y += v[q].y; }
        }
        for (; e < end; e++) {
            int s = g_src[e];
            float2 v = __half22float2(*(const __half2*)(H + s * HID + c));
            a[0].x += v.x; a[0].y += v.y;
        }

        float sx = ((a[0].x + a[1].x) + (a[2].x + a[3].x)) +
                   ((a[4].x + a[5].x) + (a[6].x + a[7].x));
        float sy = ((a[0].y + a[1].y) + (a[2].y + a[3].y)) +
                   ((a[4].y + a[5].y) + (a[6].y + a[7].y));

        float di = g_dinv[node];
        float vx = (sx * di + bx - mx) * scx + btx;
        float vy = (sy * di + by - my) * scy + bty;
        vx = fmaxf(vx, 0.0f);
        vy = fmaxf(vy, 0.0f);

        if (layer == 0) {
            *(__half2*)&g_x1[node * HID + c] = __floats2half2_rn(vx, vy);
        } else if (layer == 1) {
            float2 r = __half22float2(*(const __half2*)&g_x1[node * HID + c]);
            *(__half2*)&g_x2[node * HID + c] = __floats2half2_rn(vx + r.x, vy + r.y);
        } else {
            float2 r = __half22float2(*(const __half2*)&g_x2[node * HID + c]);
            *(float2*)(out_final + node * HID + c) = make_float2(vx + r.x, vy + r.y);
        }
    }
}

// ---------------- launch -----------------------------------------------------
extern "C" void kernel_launch(void* const* d_in, const int* in_sizes, int n_in,
                              void* d_out, int out_size) {
    const float* x   = (const float*)d_in[0];
    const int*   ei  = (const int*)d_in[1];     // int32 (JAX default, no x64)
    const float* W1  = (const float*)d_in[2];
    const float* W2  = (const float*)d_in[3];
    const float* W3  = (const float*)d_in[4];
    const float* b   = (const float*)d_in[5];
    const float* gma = (const float*)d_in[6];
    const float* bta = (const float*)d_in[7];
    const float* mu  = (const float*)d_in[8];
    const float* var = (const float*)d_in[9];
    float* out = (float*)d_out;

    // side stream + fork/join events (host resources, created once; no device alloc)
    static cudaStream_t s2 = nullptr;
    static cudaEvent_t ev1 = nullptr, ev2 = nullptr;
    if (!s2) {
        cudaStreamCreateWithFlags(&s2, cudaStreamNonBlocking);
        cudaEventCreateWithFlags(&ev1, cudaEventDisableTiming);
        cudaEventCreateWithFlags(&ev2, cudaEventDisableTiming);
    }

    void* deg_ptr = nullptr;
    cudaGetSymbolAddress(&deg_ptr, g_deg);
    cudaMemsetAsync(deg_ptr, 0, NN * sizeof(int));

    count_kernel<<<CNT_BLKS + 48, 256>>>((const int4*)(ei + EE), W1, W2, W3);
    partials_kernel<<<NBLK, 256>>>();

    const int GEMM_BLOCKS = (NN + 63) / 64;
    const int SPMM_BLOCKS = ((NN + 3) / 4 * 32 + 255) / 256;

    // fork: GEMM0 (needs g_wt + g_dinv + x only) runs concurrent with scan+bin
    cudaEventRecord(ev1, 0);
    cudaStreamWaitEvent(s2, ev1, 0);
    gemm_mma_kernel<37><<<GEMM_BLOCKS, 128, 0, s2>>>(x, 0);
    cudaEventRecord(ev2, s2);

    scan_chunks_kernel<<<NBLK, 256>>>();
    bin_kernel<<<(EE + 255) / 256, 256>>>(ei);

    // join: SpMM0 needs CSR (stream 0) and g_h (s2)
    cudaStreamWaitEvent(0, ev2, 0);

    spmm_epi_kernel<<<SPMM_BLOCKS, 256>>>(0, b,       gma,       bta,       mu,       var,       out);
    gemm_mma_kernel<64><<<GEMM_BLOCKS, 128>>>(nullptr, 1);
    spmm_epi_kernel<<<SPMM_BLOCKS, 256>>>(1, b + 64,  gma + 64,  bta + 64,  mu + 64,  var + 64,  out);
    gemm_mma_kernel<64><<<GEMM_BLOCKS, 128>>>(nullptr, 2);
    spmm_epi_kernel<<<SPMM_BLOCKS, 256>>>(2, b + 128, gma + 128, bta + 128, mu + 128, var + 128, out);
}